// round 4
// baseline (speedup 1.0000x reference)
#include <cuda_runtime.h>
#include <stdint.h>

#define BS 32
#define N 512
#define IN_X 16
#define IN_E 5
#define IN_C 3
#define IN_BD 3
#define OUT_X 16
#define OUT_E 5
#define OUT_C 3
#define OUT_BD 3

#define XCAT_OFF   0
#define XCAT_SZ    (BS * N * (IN_X + OUT_X))          // 524288
#define CCAT_OFF   (XCAT_OFF + XCAT_SZ)
#define CCAT_SZ    (BS * N * (IN_C + OUT_C))          // 98304
#define E1_OFF     (CCAT_OFF + CCAT_SZ)               // 622592
#define E1_SZ      (BS * N * N * OUT_E)               // 41943040
#define E2_OFF     (E1_OFF + E1_SZ)
#define BD1_OFF    (E2_OFF + E1_SZ)

#define ROWS_PB    8                                   // rows per block
#define BLOCKS_PER_SAMPLE (N / ROWS_PB)                // 64

// ---------------------------------------------------------------------------
// One block per (sample i, 8 consecutive reactant rows). Prep (alignment map)
// runs once per block, amortized over 8 rows of output.
// ---------------------------------------------------------------------------
__global__ __launch_bounds__(256) void fused_kernel(
    const float* __restrict__ X,
    const float* __restrict__ E,
    const float* __restrict__ AC,
    const float* __restrict__ BD,
    const int*   __restrict__ AMN,
    const int*   __restrict__ MA,
    float* __restrict__ out)
{
    __shared__ int s_amn[N];
    __shared__ int s_ma[N];
    __shared__ int s_table[N + 1];      // table[m] = product pos + 1
    __shared__ int s_sp[N];             // prodpos per reactant slot
    __shared__ int s_max;

    const int b      = blockIdx.x;
    const int i      = b / BLOCKS_PER_SAMPLE;
    const int j1base = (b % BLOCKS_PER_SAMPLE) * ROWS_PB;
    const int tid    = threadIdx.x;

    // ---- per-sample alignment prep (once per 8 rows) ----
    if (tid == 0) { s_max = -2147483647; s_table[N] = 0; }
    int mymax = -2147483647;
    #pragma unroll
    for (int k = 0; k < N / 256; k++) {
        const int j = tid + k * 256;
        const int a = AMN[i * N + j];
        const int m = MA[i * N + j];
        s_amn[j] = a;
        s_ma[j]  = m;
        s_table[j] = 0;
        mymax = max(mymax, m);
    }
    #pragma unroll
    for (int off = 16; off; off >>= 1)
        mymax = max(mymax, __shfl_xor_sync(0xffffffffu, mymax, off));
    __syncthreads();
    if ((tid & 31) == 0) atomicMax(&s_max, mymax);
    __syncthreads();
    const int pa = s_max;

    // product-side scatter: table[amn] = j+1
    #pragma unroll
    for (int k = 0; k < N / 256; k++) {
        const int j = tid + k * 256;
        const int a = s_amn[j];
        if (s_ma[j] == pa && a > 0 && a <= N) s_table[a] = j + 1;
    }
    __syncthreads();

    // full prodpos table
    #pragma unroll
    for (int k = 0; k < N / 256; k++) {
        const int j = tid + k * 256;
        const int a = s_amn[j];
        int pp = -1;
        if (s_ma[j] < pa && a > 0 && a <= N) {
            const int t = s_table[a];
            if (t > 0) pp = t - 1;
        }
        s_sp[j] = pp;
    }
    __syncthreads();

    // ---- node features for the 8 rows ----
    // X_cat: 8 rows x 32 channels = 256 floats, one per thread
    {
        const int r   = tid >> 5;              // 0..7
        const int c   = tid & 31;              // 0..31
        const int row = (i * N) + j1base + r;
        const int p1  = s_sp[j1base + r];
        float v;
        if (c < IN_X) v = X[row * IN_X + c];
        else          v = (p1 >= 0) ? __ldg(&X[(i * N + p1) * IN_X + (c - IN_X)]) : 0.0f;
        out[XCAT_OFF + row * (IN_X + OUT_X) + c] = v;
    }
    // C_cat: 8 rows x 6 channels = 48 floats
    if (tid < ROWS_PB * 6) {
        const int r   = tid / 6;
        const int c   = tid - r * 6;
        const int row = (i * N) + j1base + r;
        const int p1  = s_sp[j1base + r];
        float v;
        if (c < IN_C) v = AC[row * IN_C + c];
        else          v = (p1 >= 0) ? __ldg(&AC[(i * N + p1) * IN_C + (c - IN_C)]) : 0.0f;
        out[CCAT_OFF + row * (IN_C + OUT_C) + c] = v;
    }

    // ---- edge features: 8 rows ----
    const float4 z4 = make_float4(0.f, 0.f, 0.f, 0.f);
    float4 pat[5];
    pat[0] = make_float4(1.f, 0.f, 0.f, 0.f);
    pat[1] = make_float4(0.f, 1.f, 0.f, 0.f);
    pat[2] = make_float4(0.f, 0.f, 1.f, 0.f);
    pat[3] = make_float4(0.f, 0.f, 0.f, 1.f);
    pat[4] = z4;

    #pragma unroll 1
    for (int r = 0; r < ROWS_PB; r++) {
        const int row = (i * N) + j1base + r;
        const int p1  = s_sp[j1base + r];

        float4* __restrict__ e1v = reinterpret_cast<float4*>(out + E1_OFF  + (size_t)row * (N * OUT_E));
        float4* __restrict__ e2v = reinterpret_cast<float4*>(out + E2_OFF  + (size_t)row * (N * OUT_E));
        float4* __restrict__ bdv = reinterpret_cast<float4*>(out + BD1_OFF + (size_t)row * (N * OUT_BD));

        if (p1 < 0) {
            // unmapped row: pure vectorized fills
            #pragma unroll
            for (int k = tid; k < (N * OUT_E) / 4; k += 256) {   // 640 vecs
                __stcs(&e1v[k], z4);
                __stcs(&e2v[k], pat[k % 5]);
            }
            #pragma unroll
            for (int k = tid; k < (N * OUT_BD) / 4; k += 256) {  // 384 vecs
                __stcs(&bdv[k], z4);
            }
            continue;
        }

        // mapped row: gather product edges (scattered __ldg, L2-resident)
        const float* __restrict__ Erow  = E  + (size_t)(i * N + p1) * N * IN_E;
        const float* __restrict__ BDrow = BD + (size_t)(i * N + p1) * N * IN_BD;

        for (int k = tid; k < (N * OUT_E) / 4; k += 256) {       // 640 vecs
            float v1[4], v2[4];
            const int e0 = 4 * k;
            #pragma unroll
            for (int c4 = 0; c4 < 4; c4++) {
                const int ee = e0 + c4;
                const int j2 = ee / 5;
                const int c  = ee - j2 * 5;
                const int p2 = s_sp[j2];
                if (p2 >= 0) {
                    v1[c4] = __ldg(&Erow[p2 * IN_E + c]);
                    v2[c4] = 0.0f;
                } else {
                    v1[c4] = 0.0f;
                    v2[c4] = (c == 0) ? 1.0f : 0.0f;
                }
            }
            __stcs(&e1v[k], make_float4(v1[0], v1[1], v1[2], v1[3]));
            __stcs(&e2v[k], make_float4(v2[0], v2[1], v2[2], v2[3]));
        }

        for (int k = tid; k < (N * OUT_BD) / 4; k += 256) {      // 384 vecs
            float v[4];
            const int e0 = 4 * k;
            #pragma unroll
            for (int c4 = 0; c4 < 4; c4++) {
                const int ee = e0 + c4;
                const int j2 = ee / 3;
                const int c  = ee - j2 * 3;
                const int p2 = s_sp[j2];
                v[c4] = (p2 >= 0) ? __ldg(&BDrow[p2 * IN_BD + c]) : 0.0f;
            }
            __stcs(&bdv[k], make_float4(v[0], v[1], v[2], v[3]));
        }
    }
}

// ---------------------------------------------------------------------------
extern "C" void kernel_launch(void* const* d_in, const int* in_sizes, int n_in,
                              void* d_out, int out_size) {
    const float* X   = (const float*)d_in[0];
    const float* E   = (const float*)d_in[1];
    const float* AC  = (const float*)d_in[2];
    const float* BD  = (const float*)d_in[3];
    const int*   AMN = (const int*)d_in[4];
    const int*   MA  = (const int*)d_in[5];
    float* out = (float*)d_out;

    fused_kernel<<<(BS * N) / ROWS_PB, 256>>>(X, E, AC, BD, AMN, MA, out);
}

// round 5
// speedup vs baseline: 1.1227x; 1.1227x over previous
#include <cuda_runtime.h>
#include <stdint.h>

#define BS 32
#define N 512
#define IN_X 16
#define IN_E 5
#define IN_C 3
#define IN_BD 3
#define OUT_X 16
#define OUT_E 5
#define OUT_C 3
#define OUT_BD 3

#define XCAT_OFF   0
#define XCAT_SZ    (BS * N * (IN_X + OUT_X))          // 524288
#define CCAT_OFF   (XCAT_OFF + XCAT_SZ)
#define CCAT_SZ    (BS * N * (IN_C + OUT_C))          // 98304
#define E1_OFF     (CCAT_OFF + CCAT_SZ)               // 622592
#define E1_SZ      (BS * N * N * OUT_E)               // 41943040
#define E2_OFF     (E1_OFF + E1_SZ)
#define BD1_OFF    (E2_OFF + E1_SZ)

#define ROWS_PB    2
#define BLOCKS_PER_SAMPLE (N / ROWS_PB)                // 256

// ---------------------------------------------------------------------------
// One block = (sample i, 2 reactant rows processed in PARALLEL by half-blocks).
// Prep once per block; warps 0-3 handle row A, warps 4-7 handle row B.
// ---------------------------------------------------------------------------
__global__ __launch_bounds__(256, 6) void fused_kernel(
    const float* __restrict__ X,
    const float* __restrict__ E,
    const float* __restrict__ AC,
    const float* __restrict__ BD,
    const int*   __restrict__ AMN,
    const int*   __restrict__ MA,
    float* __restrict__ out)
{
    __shared__ int s_table[N + 1];      // table[m] = product pos + 1
    __shared__ int s_sp[N + 1];         // prodpos per reactant slot (+pad)
    __shared__ int s_max;

    const int b      = blockIdx.x;
    const int i      = b >> 8;                       // / BLOCKS_PER_SAMPLE
    const int j1base = (b & (BLOCKS_PER_SAMPLE - 1)) * ROWS_PB;
    const int tid    = threadIdx.x;

    // ---- per-sample alignment prep ----
    int a0, m0, a1, m1;
    {
        const int j0 = tid, j1 = tid + 256;
        a0 = AMN[i * N + j0]; m0 = MA[i * N + j0];
        a1 = AMN[i * N + j1]; m1 = MA[i * N + j1];
        s_table[j0] = 0; s_table[j1] = 0;
        if (tid == 0) { s_max = -2147483647; s_table[N] = 0; s_sp[N] = -1; }
    }
    int mymax = max(m0, m1);
    #pragma unroll
    for (int off = 16; off; off >>= 1)
        mymax = max(mymax, __shfl_xor_sync(0xffffffffu, mymax, off));
    __syncthreads();
    if ((tid & 31) == 0) atomicMax(&s_max, mymax);
    __syncthreads();
    const int pa = s_max;

    // product-side scatter
    if (m0 == pa && a0 > 0 && a0 <= N) s_table[a0] = tid + 1;
    if (m1 == pa && a1 > 0 && a1 <= N) s_table[a1] = tid + 257;
    __syncthreads();

    // reactant-side prodpos
    {
        int pp0 = -1, pp1 = -1;
        if (m0 < pa && a0 > 0 && a0 <= N) { const int t = s_table[a0]; if (t > 0) pp0 = t - 1; }
        if (m1 < pa && a1 > 0 && a1 <= N) { const int t = s_table[a1]; if (t > 0) pp1 = t - 1; }
        s_sp[tid]       = pp0;
        s_sp[tid + 256] = pp1;
    }
    __syncthreads();

    // ---- node features for the 2 rows (64 + 12 floats) ----
    if (tid < 64) {
        const int r   = tid >> 5;
        const int c   = tid & 31;
        const int row = i * N + j1base + r;
        const int p1  = s_sp[j1base + r];
        float v;
        if (c < IN_X) v = X[row * IN_X + c];
        else          v = (p1 >= 0) ? __ldg(&X[(i * N + p1) * IN_X + (c - IN_X)]) : 0.0f;
        out[XCAT_OFF + row * (IN_X + OUT_X) + c] = v;
    } else if (tid < 64 + ROWS_PB * 6) {
        const int t2  = tid - 64;
        const int r   = t2 / 6;
        const int c   = t2 - r * 6;
        const int row = i * N + j1base + r;
        const int p1  = s_sp[j1base + r];
        float v;
        if (c < IN_C) v = AC[row * IN_C + c];
        else          v = (p1 >= 0) ? __ldg(&AC[(i * N + p1) * IN_C + (c - IN_C)]) : 0.0f;
        out[CCAT_OFF + row * (IN_C + OUT_C) + c] = v;
    }

    // ---- edge features: half-block per row ----
    const int half = tid >> 7;          // 0 or 1
    const int ht   = tid & 127;         // thread within half
    const int row  = i * N + j1base + half;
    const int p1   = s_sp[j1base + half];

    float4* __restrict__ e1v = reinterpret_cast<float4*>(out + E1_OFF  + (size_t)row * (N * OUT_E));
    float4* __restrict__ e2v = reinterpret_cast<float4*>(out + E2_OFF  + (size_t)row * (N * OUT_E));
    float4* __restrict__ bdv = reinterpret_cast<float4*>(out + BD1_OFF + (size_t)row * (N * OUT_BD));

    if (p1 < 0) {
        // unmapped row: pure vectorized fills (5 + 3 iterations)
        const float4 z4 = make_float4(0.f, 0.f, 0.f, 0.f);
        #pragma unroll
        for (int it = 0; it < 5; it++) {
            const int k = ht + it * 128;             // < 640
            const int m5 = k % 5;
            float4 p = z4;
            if      (m5 == 0) p.x = 1.f;
            else if (m5 == 1) p.y = 1.f;
            else if (m5 == 2) p.z = 1.f;
            else if (m5 == 3) p.w = 1.f;
            __stcs(&e1v[k], z4);
            __stcs(&e2v[k], p);
        }
        #pragma unroll
        for (int it = 0; it < 3; it++) {
            const int k = ht + it * 128;             // < 384
            __stcs(&bdv[k], z4);
        }
        return;
    }

    // mapped row: gather product edges (scattered __ldg, batched by unroll)
    const float* __restrict__ Erow  = E  + (size_t)(i * N + p1) * N * IN_E;
    const float* __restrict__ BDrow = BD + (size_t)(i * N + p1) * N * IN_BD;

    // E1/E2: 640 float4; 4 consecutive elems span at most 2 j2 values
    #pragma unroll
    for (int it = 0; it < 5; it++) {
        const int k  = ht + it * 128;
        const int e0 = 4 * k;
        const int q  = e0 / 5;
        const int r0 = e0 - 5 * q;
        const int pA = s_sp[q];
        const int pB = s_sp[q + 1];
        float v1[4], v2[4];
        #pragma unroll
        for (int c4 = 0; c4 < 4; c4++) {
            const int idx = r0 + c4;
            const bool hi = (idx >= 5);
            const int c   = hi ? idx - 5 : idx;
            const int p2  = hi ? pB : pA;
            if (p2 >= 0) {
                v1[c4] = __ldg(&Erow[p2 * IN_E + c]);
                v2[c4] = 0.0f;
            } else {
                v1[c4] = 0.0f;
                v2[c4] = (c == 0) ? 1.0f : 0.0f;
            }
        }
        __stcs(&e1v[k], make_float4(v1[0], v1[1], v1[2], v1[3]));
        __stcs(&e2v[k], make_float4(v2[0], v2[1], v2[2], v2[3]));
    }

    // BD1: 384 float4
    #pragma unroll
    for (int it = 0; it < 3; it++) {
        const int k  = ht + it * 128;
        const int e0 = 4 * k;
        const int q  = e0 / 3;
        const int r0 = e0 - 3 * q;
        const int pA = s_sp[q];
        const int pB = s_sp[q + 1];
        float v[4];
        #pragma unroll
        for (int c4 = 0; c4 < 4; c4++) {
            const int idx = r0 + c4;
            const bool hi = (idx >= 3);
            const int c   = hi ? idx - 3 : idx;
            const int p2  = hi ? pB : pA;
            v[c4] = (p2 >= 0) ? __ldg(&BDrow[p2 * IN_BD + c]) : 0.0f;
        }
        __stcs(&bdv[k], make_float4(v[0], v[1], v[2], v[3]));
    }
}

// ---------------------------------------------------------------------------
extern "C" void kernel_launch(void* const* d_in, const int* in_sizes, int n_in,
                              void* d_out, int out_size) {
    const float* X   = (const float*)d_in[0];
    const float* E   = (const float*)d_in[1];
    const float* AC  = (const float*)d_in[2];
    const float* BD  = (const float*)d_in[3];
    const int*   AMN = (const int*)d_in[4];
    const int*   MA  = (const int*)d_in[5];
    float* out = (float*)d_out;

    fused_kernel<<<(BS * N) / ROWS_PB, 256>>>(X, E, AC, BD, AMN, MA, out);
}

// round 6
// speedup vs baseline: 1.1503x; 1.0246x over previous
#include <cuda_runtime.h>
#include <stdint.h>

#define BS 32
#define N 512
#define IN_X 16
#define IN_E 5
#define IN_C 3
#define IN_BD 3
#define OUT_X 16
#define OUT_E 5
#define OUT_C 3
#define OUT_BD 3

#define XCAT_OFF   0
#define XCAT_SZ    (BS * N * (IN_X + OUT_X))          // 524288
#define CCAT_OFF   (XCAT_OFF + XCAT_SZ)
#define CCAT_SZ    (BS * N * (IN_C + OUT_C))          // 98304
#define E1_OFF     (CCAT_OFF + CCAT_SZ)               // 622592
#define E1_SZ      (BS * N * N * OUT_E)               // 41943040
#define E2_OFF     (E1_OFF + E1_SZ)
#define BD1_OFF    (E2_OFF + E1_SZ)

// ---------------------------------------------------------------------------
// One block per (sample i, reactant row j1). R2 shape + register-resident
// prep + lazy s_sp + dual-lookup inner loops.
// ---------------------------------------------------------------------------
__global__ __launch_bounds__(256) void fused_kernel(
    const float* __restrict__ X,
    const float* __restrict__ E,
    const float* __restrict__ AC,
    const float* __restrict__ BD,
    const int*   __restrict__ AMN,
    const int*   __restrict__ MA,
    float* __restrict__ out)
{
    __shared__ int s_table[N + 1];   // table[m] = product pos + 1 (0 = absent)
    __shared__ int s_sp[N + 1];      // prodpos per reactant slot (lazy)
    __shared__ int s_max;
    __shared__ int s_p1;

    const int b   = blockIdx.x;
    const int i   = b >> 9;
    const int j1  = b & (N - 1);
    const int tid = threadIdx.x;

    // ---- prep: load amn/ma into regs, zero table ----
    const int j0 = tid, jh = tid + 256;
    const int a0 = AMN[i * N + j0];
    const int m0 = MA[i * N + j0];
    const int a1 = AMN[i * N + jh];
    const int m1 = MA[i * N + jh];
    s_table[j0] = 0;
    s_table[jh] = 0;
    if (tid == 0) { s_max = -2147483647; s_table[N] = 0; s_sp[N] = -1; }

    int mymax = max(m0, m1);
    #pragma unroll
    for (int off = 16; off; off >>= 1)
        mymax = max(mymax, __shfl_xor_sync(0xffffffffu, mymax, off));
    __syncthreads();
    if ((tid & 31) == 0) atomicMax(&s_max, mymax);
    __syncthreads();
    const int pa = s_max;

    // product-side scatter: table[amn] = pos + 1
    if (m0 == pa && a0 > 0 && a0 <= N) s_table[a0] = j0 + 1;
    if (m1 == pa && a1 > 0 && a1 <= N) s_table[a1] = jh + 1;
    __syncthreads();

    // this row's aligned product position (owning thread broadcasts)
    if ((j1 & 255) == tid) {
        const bool hi = (j1 >= 256);
        const int  a  = hi ? a1 : a0;
        const int  m  = hi ? m1 : m0;
        int pp = -1;
        if (m < pa && a > 0 && a <= N) {
            const int t = s_table[a];
            if (t > 0) pp = t - 1;
        }
        s_p1 = pp;
    }
    __syncthreads();
    const int p1 = s_p1;

    const int row = b;
    // ---- node features (38 floats for this row) ----
    if (tid < 32) {
        float v;
        if (tid < IN_X) v = X[row * IN_X + tid];
        else            v = (p1 >= 0) ? __ldg(&X[(i * N + p1) * IN_X + (tid - IN_X)]) : 0.0f;
        out[XCAT_OFF + row * (IN_X + OUT_X) + tid] = v;
    } else if (tid < 38) {
        const int c = tid - 32;
        float v;
        if (c < IN_C) v = AC[row * IN_C + c];
        else          v = (p1 >= 0) ? __ldg(&AC[(i * N + p1) * IN_C + (c - IN_C)]) : 0.0f;
        out[CCAT_OFF + row * (IN_C + OUT_C) + c] = v;
    }

    float4* __restrict__ e1v = reinterpret_cast<float4*>(out + E1_OFF  + (size_t)row * (N * OUT_E));
    float4* __restrict__ e2v = reinterpret_cast<float4*>(out + E2_OFF  + (size_t)row * (N * OUT_E));
    float4* __restrict__ bdv = reinterpret_cast<float4*>(out + BD1_OFF + (size_t)row * (N * OUT_BD));

    if (p1 < 0) {
        // ---- unmapped row: pure vectorized fills ----
        const float4 z4 = make_float4(0.f, 0.f, 0.f, 0.f);
        float4 pat[5];
        pat[0] = make_float4(1.f, 0.f, 0.f, 0.f);
        pat[1] = make_float4(0.f, 1.f, 0.f, 0.f);
        pat[2] = make_float4(0.f, 0.f, 1.f, 0.f);
        pat[3] = make_float4(0.f, 0.f, 0.f, 1.f);
        pat[4] = z4;
        #pragma unroll
        for (int k = tid; k < (N * OUT_E) / 4; k += 256) {   // 640 vecs
            __stcs(&e1v[k], z4);
            __stcs(&e2v[k], pat[k % 5]);
        }
        #pragma unroll
        for (int k = tid; k < (N * OUT_BD) / 4; k += 256) {  // 384 vecs
            __stcs(&bdv[k], z4);
        }
        return;
    }

    // ---- mapped row: build full prodpos table (lazy), then gather ----
    {
        int pp0 = -1, pp1 = -1;
        if (m0 < pa && a0 > 0 && a0 <= N) { const int t = s_table[a0]; if (t > 0) pp0 = t - 1; }
        if (m1 < pa && a1 > 0 && a1 <= N) { const int t = s_table[a1]; if (t > 0) pp1 = t - 1; }
        s_sp[j0] = pp0;
        s_sp[jh] = pp1;
    }
    __syncthreads();

    const float* __restrict__ Erow  = E  + (size_t)(i * N + p1) * N * IN_E;
    const float* __restrict__ BDrow = BD + (size_t)(i * N + p1) * N * IN_BD;

    // E1 / E2: 640 float4; 4 consecutive elems span exactly 2 j2 values
    #pragma unroll
    for (int it = 0; it < 3; it++) {                  // covers k < 640 with stride 256
        const int k = tid + it * 256;
        if (k >= (N * OUT_E) / 4) break;
        const int e0 = 4 * k;
        const int q  = e0 / 5;
        const int r0 = e0 - 5 * q;
        const int pA = s_sp[q];
        const int pB = s_sp[q + 1];
        float v1[4], v2[4];
        #pragma unroll
        for (int c4 = 0; c4 < 4; c4++) {
            const int idx = r0 + c4;
            const bool hi = (idx >= 5);
            const int c   = hi ? idx - 5 : idx;
            const int p2  = hi ? pB : pA;
            if (p2 >= 0) {
                v1[c4] = __ldg(&Erow[p2 * IN_E + c]);
                v2[c4] = 0.0f;
            } else {
                v1[c4] = 0.0f;
                v2[c4] = (c == 0) ? 1.0f : 0.0f;
            }
        }
        __stcs(&e1v[k], make_float4(v1[0], v1[1], v1[2], v1[3]));
        __stcs(&e2v[k], make_float4(v2[0], v2[1], v2[2], v2[3]));
    }

    // BD1: 384 float4
    #pragma unroll
    for (int it = 0; it < 2; it++) {
        const int k = tid + it * 256;
        if (k >= (N * OUT_BD) / 4) break;
        const int e0 = 4 * k;
        const int q  = e0 / 3;
        const int r0 = e0 - 3 * q;
        const int pA = s_sp[q];
        const int pB = s_sp[q + 1];
        float v[4];
        #pragma unroll
        for (int c4 = 0; c4 < 4; c4++) {
            const int idx = r0 + c4;
            const bool hi = (idx >= 3);
            const int c   = hi ? idx - 3 : idx;
            const int p2  = hi ? pB : pA;
            v[c4] = (p2 >= 0) ? __ldg(&BDrow[p2 * IN_BD + c]) : 0.0f;
        }
        __stcs(&bdv[k], make_float4(v[0], v[1], v[2], v[3]));
    }
}

// ---------------------------------------------------------------------------
extern "C" void kernel_launch(void* const* d_in, const int* in_sizes, int n_in,
                              void* d_out, int out_size) {
    const float* X   = (const float*)d_in[0];
    const float* E   = (const float*)d_in[1];
    const float* AC  = (const float*)d_in[2];
    const float* BD  = (const float*)d_in[3];
    const int*   AMN = (const int*)d_in[4];
    const int*   MA  = (const int*)d_in[5];
    float* out = (float*)d_out;

    fused_kernel<<<BS * N, 256>>>(X, E, AC, BD, AMN, MA, out);
}